// round 13
// baseline (speedup 1.0000x reference)
#include <cuda_runtime.h>
#include <cuda_bf16.h>
#include <cstdint>

// GraphSAGE 2-layer encoder — CSR pull, with CSR build hidden under GEMM-1.
//
// Per layer: t = h @ [Wl | Wr]  (dense dual GEMM, row stride 128)
//            out[i] = inv_deg[i]*sum_{e in CSR[i]} t[src_e,0:64] + b + t[i,64:128] (+relu)
//
// Launch graph (single stream, merged kernels give the overlap):
//   K1: gemm1 rows [0,n/2)   blocks [0,GEMM_BLKS) ∥ hist blocks [GEMM_BLKS,...)
//   scan1 (reads g_degtmp, then re-zeroes it -> invariant for next replay)
//   scan3 (fused block-sum scan + rowptr/cursor write)
//   K2: gemm1 rows [n/2,n)   ∥ bin
//   reduce1 -> g_h (relu)
//   gemm2 (full) ; reduce2 -> out

#define MAXN 100000
#define MAXE 1600000
#define SCAN_B 512
#define GEMM_BLKS 304
#define SIDE_BLKS 912

__device__ float g_t[MAXN * 128];       // [msg cols 0..63 | root cols 64..127]
__device__ float g_h[MAXN * 64];        // layer-1 output
__device__ int   g_rowptr[MAXN + 1];
__device__ int   g_cursor[MAXN];
__device__ int   g_ssrc[MAXE];          // src ids grouped by dst
__device__ int   g_degtmp[MAXN];        // histogram accumulator (zero-invariant between launches)
__device__ int   g_scantmp[MAXN];       // per-block exclusive scan
__device__ int   g_bsums[SCAN_B];       // block sums (nb <= 196 for N=100K)

// ---- packed fp32x2 helpers --------------------------------------------------
__device__ __forceinline__ unsigned long long pack2(float x, float y) {
    unsigned long long r;
    asm("mov.b64 %0, {%1, %2};" : "=l"(r) : "f"(x), "f"(y));
    return r;
}
__device__ __forceinline__ void fma2(unsigned long long& acc,
                                     unsigned long long a, unsigned long long b) {
    asm("fma.rn.f32x2 %0, %1, %2, %0;" : "+l"(acc) : "l"(a), "l"(b));
}
__device__ __forceinline__ void unpack2(unsigned long long v, float& x, float& y) {
    asm("mov.b64 {%0, %1}, %2;" : "=f"(x), "=f"(y) : "l"(v));
}

// ---------------------------------------------------------------------------
// GEMM body: t[row, 0:128] = h[row, :] @ [Wl | Wr] over rows [rbeg, rend).
// 128 threads, one output column/thread; 8 rows/iter, pair-interleaved smem,
// inner loop per k: 4x LDS.64 broadcast + pack + 4x FFMA2.
// ---------------------------------------------------------------------------
__device__ __forceinline__ void gemm_body(
    const float* __restrict__ h,
    const float* __restrict__ wl, const float* __restrict__ wr,
    int rbeg, int rend, int bid, int nblocks, float* xs /* 512 floats smem */)
{
    const int col = threadIdx.x;  // 0..127
    float w[64];
#pragma unroll
    for (int k = 0; k < 64; k++)
        w[k] = (col < 64) ? __ldg(wl + k * 64 + col) : __ldg(wr + k * 64 + (col - 64));

    for (int row0 = rbeg + bid * 8; row0 < rend; row0 += nblocks * 8) {
        __syncthreads();
#pragma unroll
        for (int i = 0; i < 4; i++) {
            int idx = threadIdx.x + i * 128;        // 0..511
            int rr = idx >> 6, k = idx & 63;        // rr: 0..7
            int row = row0 + rr;
            float val = (row < rend) ? __ldg(h + (size_t)row * 64 + k) : 0.f;
            xs[(rr >> 1) * 128 + k * 2 + (rr & 1)] = val;
        }
        __syncthreads();

        unsigned long long a0 = 0ull, a1 = 0ull, a2 = 0ull, a3 = 0ull;
        const unsigned long long* xp = reinterpret_cast<const unsigned long long*>(xs);
#pragma unroll
        for (int k = 0; k < 64; k++) {
            const unsigned long long wkk = pack2(w[k], w[k]);
            fma2(a0, xp[k], wkk);
            fma2(a1, xp[64 + k], wkk);
            fma2(a2, xp[128 + k], wkk);
            fma2(a3, xp[192 + k], wkk);
        }

        float r[8];
        unpack2(a0, r[0], r[1]);
        unpack2(a1, r[2], r[3]);
        unpack2(a2, r[4], r[5]);
        unpack2(a3, r[6], r[7]);
#pragma unroll
        for (int j = 0; j < 8; j++)
            if (row0 + j < rend) g_t[(size_t)(row0 + j) * 128 + col] = r[j];
    }
}

// ---------------------------------------------------------------------------
// K1: gemm1 over rows [0, rsplit)  ∥  degree histogram
// ---------------------------------------------------------------------------
__global__ void __launch_bounds__(128) k1_gemm_hist(
    const float* __restrict__ x,
    const float* __restrict__ wl, const float* __restrict__ wr,
    const int* __restrict__ dst, int rsplit, int ne)
{
    __shared__ float xs[512];
    if (blockIdx.x < GEMM_BLKS) {
        gemm_body(x, wl, wr, 0, rsplit, blockIdx.x, GEMM_BLKS, xs);
    } else {
        const int bid = blockIdx.x - GEMM_BLKS;
        const int stride = SIDE_BLKS * 128;
        for (int e = bid * 128 + threadIdx.x; e < ne; e += stride)
            atomicAdd(&g_degtmp[__ldg(dst + e)], 1);
    }
}

// ---------------------------------------------------------------------------
// scan1: per-block exclusive scan of g_degtmp + block totals; re-zeroes degtmp.
// ---------------------------------------------------------------------------
__global__ void __launch_bounds__(SCAN_B) scan1_kernel(int n) {
    __shared__ int sh[SCAN_B];
    const int tid = threadIdx.x;
    const int i = blockIdx.x * SCAN_B + tid;
    int v = (i < n) ? g_degtmp[i] : 0;
    sh[tid] = v;
    __syncthreads();
#pragma unroll
    for (int o = 1; o < SCAN_B; o <<= 1) {
        int t = (tid >= o) ? sh[tid - o] : 0;
        __syncthreads();
        sh[tid] += t;
        __syncthreads();
    }
    if (i < n) {
        g_scantmp[i] = sh[tid] - v;                 // exclusive
        g_degtmp[i] = 0;                            // restore zero-invariant
    }
    if (tid == SCAN_B - 1) g_bsums[blockIdx.x] = sh[tid];
}

// Fused: each block scans g_bsums (nb <= 256) in smem, then writes rowptr.
__global__ void __launch_bounds__(256) scan3_kernel(int n, int ne, int nb) {
    __shared__ int sb[256];
    __shared__ int se[256];
    const int tid = threadIdx.x;
    int v = (tid < nb) ? g_bsums[tid] : 0;
    sb[tid] = v;
    __syncthreads();
#pragma unroll
    for (int o = 1; o < 256; o <<= 1) {
        int t = (tid >= o) ? sb[tid - o] : 0;
        __syncthreads();
        sb[tid] += t;
        __syncthreads();
    }
    se[tid] = sb[tid] - v;                          // exclusive block offset
    __syncthreads();

    const int i = blockIdx.x * blockDim.x + tid;
    if (i < n) {
        int rp = g_scantmp[i] + se[i / SCAN_B];
        g_rowptr[i] = rp;
        g_cursor[i] = rp;
    }
    if (i == 0) g_rowptr[n] = ne;
}

// ---------------------------------------------------------------------------
// K2: gemm1 over rows [rsplit, n)  ∥  edge binning into g_ssrc
// ---------------------------------------------------------------------------
__global__ void __launch_bounds__(128) k2_gemm_bin(
    const float* __restrict__ x,
    const float* __restrict__ wl, const float* __restrict__ wr,
    const int* __restrict__ src, const int* __restrict__ dst,
    int rsplit, int n, int ne)
{
    __shared__ float xs[512];
    if (blockIdx.x < GEMM_BLKS) {
        gemm_body(x, wl, wr, rsplit, n, blockIdx.x, GEMM_BLKS, xs);
    } else {
        const int bid = blockIdx.x - GEMM_BLKS;
        const int stride = SIDE_BLKS * 128;
        for (int e = bid * 128 + threadIdx.x; e < ne; e += stride) {
            int d = __ldg(dst + e);
            int pos = atomicAdd(&g_cursor[d], 1);
            g_ssrc[pos] = __ldg(src + e);
        }
    }
}

// ---------------------------------------------------------------------------
// Layer-2 full GEMM (dedicated)
// ---------------------------------------------------------------------------
__global__ void __launch_bounds__(128) gemm2_kernel(
    const float* __restrict__ wl, const float* __restrict__ wr, int n)
{
    __shared__ float xs[512];
    gemm_body(g_h, wl, wr, 0, n, blockIdx.x, gridDim.x, xs);
}

// ---------------------------------------------------------------------------
// CSR reduce + fused epilogue. One warp per node; lane owns cols [2l, 2l+1].
// ---------------------------------------------------------------------------
__global__ void __launch_bounds__(256) csr_reduce_kernel(
    const float* __restrict__ bias, float* __restrict__ out_ext,
    int n, int layer)
{
    float* __restrict__ out = (layer == 0) ? g_h : out_ext;
    const int do_relu = (layer == 0);
    const int warp = (blockIdx.x * blockDim.x + threadIdx.x) >> 5;
    const int lane = threadIdx.x & 31;
    if (warp >= n) return;
    const int i = warp;

    const int beg = __ldg(g_rowptr + i);
    const int end = __ldg(g_rowptr + i + 1);
    const int c2 = lane * 2;

    float ax = 0.f, ay = 0.f;
    int e = beg;
    for (; e + 8 <= end; e += 8) {
        int s[8];
#pragma unroll
        for (int j = 0; j < 8; j++) s[j] = __ldg(g_ssrc + e + j);
        float2 v[8];
#pragma unroll
        for (int j = 0; j < 8; j++)
            v[j] = *reinterpret_cast<const float2*>(g_t + (size_t)s[j] * 128 + c2);
#pragma unroll
        for (int j = 0; j < 8; j++) {
            ax += v[j].x;
            ay += v[j].y;
        }
    }
    for (; e < end; e++) {
        const int s = __ldg(g_ssrc + e);
        const float2 v = *reinterpret_cast<const float2*>(g_t + (size_t)s * 128 + c2);
        ax += v.x;
        ay += v.y;
    }

    const float inv = 1.0f / fmaxf((float)(end - beg), 1.0f);
    const float2 r = *reinterpret_cast<const float2*>(g_t + (size_t)i * 128 + 64 + c2);
    const float2 b = *reinterpret_cast<const float2*>(bias + c2);
    float ox = fmaf(inv, ax, b.x + r.x);
    float oy = fmaf(inv, ay, b.y + r.y);
    if (do_relu) {
        ox = fmaxf(ox, 0.f);
        oy = fmaxf(oy, 0.f);
    }
    *reinterpret_cast<float2*>(out + (size_t)i * 64 + c2) = make_float2(ox, oy);
}

// ---------------------------------------------------------------------------
// Launch.  Inputs: x [N*64] f32, edge_index [2*E] i32, w1l, b1l, w1r, w2l, b2l, w2r
// Output: [N*64] f32
// ---------------------------------------------------------------------------
extern "C" void kernel_launch(void* const* d_in, const int* in_sizes, int n_in,
                              void* d_out, int out_size) {
    const float* x   = (const float*)d_in[0];
    const int*   ei  = (const int*)d_in[1];
    const float* w1l = (const float*)d_in[2];
    const float* b1l = (const float*)d_in[3];
    const float* w1r = (const float*)d_in[4];
    const float* w2l = (const float*)d_in[5];
    const float* b2l = (const float*)d_in[6];
    const float* w2r = (const float*)d_in[7];
    float* out = (float*)d_out;

    const int n  = in_sizes[0] / 64;
    const int ne = in_sizes[1] / 2;
    const int* src = ei;
    const int* dst = ei + ne;

    const int nb = (n + SCAN_B - 1) / SCAN_B;   // <= 196 for N=100K
    const int rsplit = (n / 2 + 7) & ~7;        // 8-aligned split of gemm1 rows

    // K1: gemm1 first half ∥ degree histogram (g_degtmp is zero on entry:
    // zero-initialized at load, re-zeroed by scan1 every launch)
    k1_gemm_hist<<<GEMM_BLKS + SIDE_BLKS, 128>>>(x, w1l, w1r, dst, rsplit, ne);
    scan1_kernel<<<nb, SCAN_B>>>(n);
    scan3_kernel<<<(n + 255) / 256, 256>>>(n, ne, nb);
    // K2: gemm1 second half ∥ edge binning
    k2_gemm_bin<<<GEMM_BLKS + SIDE_BLKS, 128>>>(x, w1l, w1r, src, dst, rsplit, n, ne);

    const int rblocks = (n * 32 + 255) / 256;  // one warp per node

    csr_reduce_kernel<<<rblocks, 256>>>(b1l, out, n, 0);

    gemm2_kernel<<<608, 128>>>(w2l, w2r, n);
    csr_reduce_kernel<<<rblocks, 256>>>(b2l, out, n, 1);
}

// round 15
// speedup vs baseline: 1.0389x; 1.0389x over previous
#include <cuda_runtime.h>
#include <cuda_bf16.h>
#include <cuda_fp16.h>
#include <cstdint>

// GraphSAGE 2-layer encoder — CSR pull, fp16 message storage (fp32 accumulate).
//
// Per layer: tmsg = fp16(h @ Wl), troot = fp32(h @ Wr)   (dual GEMM)
//            out[i] = inv_deg[i]*sum_e fp32(tmsg[src_e]) + b + troot[i] (+relu)
// CSR built per launch (hist -> scan -> bin); scan1 re-zeroes the histogram
// to keep the zero-invariant across graph replays.

#define MAXN 100000
#define MAXE 1600000
#define SCAN_B 512

__device__ __half g_tmsg[MAXN * 64];    // message half of t (fp16, gathered randomly)
__device__ float  g_troot[MAXN * 64];   // root half of t (fp32, read densely once)
__device__ float  g_h[MAXN * 64];       // layer-1 output
__device__ int    g_rowptr[MAXN + 1];
__device__ int    g_cursor[MAXN];
__device__ int    g_ssrc[MAXE];         // src ids grouped by dst
__device__ int    g_degtmp[MAXN];       // histogram accumulator (zero-invariant)
__device__ int    g_scantmp[MAXN];      // per-block exclusive scan
__device__ int    g_bsums[SCAN_B];      // block sums (nb <= 196 for N=100K)

// ---- packed fp32x2 helpers --------------------------------------------------
__device__ __forceinline__ unsigned long long pack2(float x, float y) {
    unsigned long long r;
    asm("mov.b64 %0, {%1, %2};" : "=l"(r) : "f"(x), "f"(y));
    return r;
}
__device__ __forceinline__ void fma2(unsigned long long& acc,
                                     unsigned long long a, unsigned long long b) {
    asm("fma.rn.f32x2 %0, %1, %2, %0;" : "+l"(acc) : "l"(a), "l"(b));
}
__device__ __forceinline__ void unpack2(unsigned long long v, float& x, float& y) {
    asm("mov.b64 {%0, %1}, %2;" : "=f"(x), "=f"(y) : "l"(v));
}

// ---------------------------------------------------------------------------
// CSR construction
// ---------------------------------------------------------------------------
__global__ void hist_kernel(const int* __restrict__ dst, int ne) {
    const int stride = gridDim.x * blockDim.x;
    for (int e = blockIdx.x * blockDim.x + threadIdx.x; e < ne; e += stride)
        atomicAdd(&g_degtmp[__ldg(dst + e)], 1);
}

// Per-block exclusive scan of g_degtmp + block totals; re-zeroes degtmp.
__global__ void __launch_bounds__(SCAN_B) scan1_kernel(int n) {
    __shared__ int sh[SCAN_B];
    const int tid = threadIdx.x;
    const int i = blockIdx.x * SCAN_B + tid;
    int v = (i < n) ? g_degtmp[i] : 0;
    sh[tid] = v;
    __syncthreads();
#pragma unroll
    for (int o = 1; o < SCAN_B; o <<= 1) {
        int t = (tid >= o) ? sh[tid - o] : 0;
        __syncthreads();
        sh[tid] += t;
        __syncthreads();
    }
    if (i < n) {
        g_scantmp[i] = sh[tid] - v;                 // exclusive
        g_degtmp[i] = 0;                            // restore zero-invariant
    }
    if (tid == SCAN_B - 1) g_bsums[blockIdx.x] = sh[tid];
}

// Fused: each block scans g_bsums (nb <= 256) in smem, then writes rowptr.
__global__ void __launch_bounds__(256) scan3_kernel(int n, int ne, int nb) {
    __shared__ int sb[256];
    __shared__ int se[256];
    const int tid = threadIdx.x;
    int v = (tid < nb) ? g_bsums[tid] : 0;
    sb[tid] = v;
    __syncthreads();
#pragma unroll
    for (int o = 1; o < 256; o <<= 1) {
        int t = (tid >= o) ? sb[tid - o] : 0;
        __syncthreads();
        sb[tid] += t;
        __syncthreads();
    }
    se[tid] = sb[tid] - v;                          // exclusive block offset
    __syncthreads();

    const int i = blockIdx.x * blockDim.x + tid;
    if (i < n) {
        int rp = g_scantmp[i] + se[i / SCAN_B];
        g_rowptr[i] = rp;
        g_cursor[i] = rp;
    }
    if (i == 0) g_rowptr[n] = ne;
}

__global__ void bin_kernel(const int* __restrict__ src,
                           const int* __restrict__ dst, int ne) {
    const int stride = gridDim.x * blockDim.x;
    for (int e = blockIdx.x * blockDim.x + threadIdx.x; e < ne; e += stride) {
        int d = __ldg(dst + e);
        int pos = atomicAdd(&g_cursor[d], 1);
        g_ssrc[pos] = __ldg(src + e);
    }
}

// ---------------------------------------------------------------------------
// Dual GEMM: msg col (0..63) -> fp16 g_tmsg, root col (64..127) -> fp32 g_troot.
// 128 threads/block, one output column/thread; 8 rows/iter, pair-interleaved
// smem, inner loop per k: 4x LDS.64 broadcast + pack + 4x FFMA2.
// ---------------------------------------------------------------------------
__global__ void __launch_bounds__(128) gemm_dual_kernel(
    const float* __restrict__ x,
    const float* __restrict__ wl, const float* __restrict__ wr,
    int n, int layer)
{
    const float* __restrict__ h = (layer == 0) ? x : g_h;
    __shared__ float xs[4 * 64 * 2];   // pair-major: xs[p*128 + k*2 + half]
    const int col = threadIdx.x;       // 0..127
    const int is_msg = (col < 64);

    float w[64];
#pragma unroll
    for (int k = 0; k < 64; k++)
        w[k] = is_msg ? __ldg(wl + k * 64 + col) : __ldg(wr + k * 64 + (col - 64));

    for (int row0 = blockIdx.x * 8; row0 < n; row0 += gridDim.x * 8) {
        __syncthreads();
#pragma unroll
        for (int i = 0; i < 4; i++) {
            int idx = threadIdx.x + i * 128;        // 0..511
            int rr = idx >> 6, k = idx & 63;        // rr: 0..7
            int row = row0 + rr;
            float val = (row < n) ? __ldg(h + (size_t)row * 64 + k) : 0.f;
            xs[(rr >> 1) * 128 + k * 2 + (rr & 1)] = val;
        }
        __syncthreads();

        unsigned long long a0 = 0ull, a1 = 0ull, a2 = 0ull, a3 = 0ull;
        const unsigned long long* xp = reinterpret_cast<const unsigned long long*>(xs);
#pragma unroll
        for (int k = 0; k < 64; k++) {
            const unsigned long long wkk = pack2(w[k], w[k]);
            fma2(a0, xp[k], wkk);
            fma2(a1, xp[64 + k], wkk);
            fma2(a2, xp[128 + k], wkk);
            fma2(a3, xp[192 + k], wkk);
        }

        float r[8];
        unpack2(a0, r[0], r[1]);
        unpack2(a1, r[2], r[3]);
        unpack2(a2, r[4], r[5]);
        unpack2(a3, r[6], r[7]);
        if (is_msg) {
#pragma unroll
            for (int j = 0; j < 8; j++)
                if (row0 + j < n)
                    g_tmsg[(size_t)(row0 + j) * 64 + col] = __float2half_rn(r[j]);
        } else {
#pragma unroll
            for (int j = 0; j < 8; j++)
                if (row0 + j < n)
                    g_troot[(size_t)(row0 + j) * 64 + (col - 64)] = r[j];
        }
    }
}

// ---------------------------------------------------------------------------
// CSR reduce + fused epilogue. One warp per node; lane owns cols [2l, 2l+1].
// Gather is half2 (4B/lane/edge = 128B/edge); accumulation in fp32.
// ---------------------------------------------------------------------------
__global__ void __launch_bounds__(256) csr_reduce_kernel(
    const float* __restrict__ bias, float* __restrict__ out_ext,
    int n, int layer)
{
    float* __restrict__ out = (layer == 0) ? g_h : out_ext;
    const int do_relu = (layer == 0);
    const int warp = (blockIdx.x * blockDim.x + threadIdx.x) >> 5;
    const int lane = threadIdx.x & 31;
    if (warp >= n) return;
    const int i = warp;

    const int beg = __ldg(g_rowptr + i);
    const int end = __ldg(g_rowptr + i + 1);
    const int c2 = lane * 2;

    float ax = 0.f, ay = 0.f;
    int e = beg;
    for (; e + 8 <= end; e += 8) {
        int s[8];
#pragma unroll
        for (int j = 0; j < 8; j++) s[j] = __ldg(g_ssrc + e + j);
        half2 v[8];
#pragma unroll
        for (int j = 0; j < 8; j++)
            v[j] = *reinterpret_cast<const half2*>(g_tmsg + (size_t)s[j] * 64 + c2);
#pragma unroll
        for (int j = 0; j < 8; j++) {
            float2 f = __half22float2(v[j]);
            ax += f.x;
            ay += f.y;
        }
    }
    for (; e < end; e++) {
        const int s = __ldg(g_ssrc + e);
        float2 f = __half22float2(
            *reinterpret_cast<const half2*>(g_tmsg + (size_t)s * 64 + c2));
        ax += f.x;
        ay += f.y;
    }

    const float inv = 1.0f / fmaxf((float)(end - beg), 1.0f);
    const float2 r = *reinterpret_cast<const float2*>(g_troot + (size_t)i * 64 + c2);
    const float2 b = *reinterpret_cast<const float2*>(bias + c2);
    float ox = fmaf(inv, ax, b.x + r.x);
    float oy = fmaf(inv, ay, b.y + r.y);
    if (do_relu) {
        ox = fmaxf(ox, 0.f);
        oy = fmaxf(oy, 0.f);
    }
    *reinterpret_cast<float2*>(out + (size_t)i * 64 + c2) = make_float2(ox, oy);
}

// ---------------------------------------------------------------------------
// Launch.  Inputs: x [N*64] f32, edge_index [2*E] i32, w1l, b1l, w1r, w2l, b2l, w2r
// Output: [N*64] f32
// ---------------------------------------------------------------------------
extern "C" void kernel_launch(void* const* d_in, const int* in_sizes, int n_in,
                              void* d_out, int out_size) {
    const float* x   = (const float*)d_in[0];
    const int*   ei  = (const int*)d_in[1];
    const float* w1l = (const float*)d_in[2];
    const float* b1l = (const float*)d_in[3];
    const float* w1r = (const float*)d_in[4];
    const float* w2l = (const float*)d_in[5];
    const float* b2l = (const float*)d_in[6];
    const float* w2r = (const float*)d_in[7];
    float* out = (float*)d_out;

    const int n  = in_sizes[0] / 64;
    const int ne = in_sizes[1] / 2;
    const int* src = ei;
    const int* dst = ei + ne;

    const int nb = (n + SCAN_B - 1) / SCAN_B;   // <= 196 for N=100K

    // CSR build (g_degtmp zero on entry: zeroed at load, re-zeroed by scan1)
    hist_kernel<<<1216, 256>>>(dst, ne);
    scan1_kernel<<<nb, SCAN_B>>>(n);
    scan3_kernel<<<(n + 255) / 256, 256>>>(n, ne, nb);
    bin_kernel<<<1216, 256>>>(src, dst, ne);

    const int rblocks = (n * 32 + 255) / 256;  // one warp per node

    // Layer 1
    gemm_dual_kernel<<<608, 128>>>(x, w1l, w1r, n, 0);
    csr_reduce_kernel<<<rblocks, 256>>>(b1l, out, n, 0);

    // Layer 2
    gemm_dual_kernel<<<608, 128>>>(x, w2l, w2r, n, 1);
    csr_reduce_kernel<<<rblocks, 256>>>(b2l, out, n, 1);
}